// round 13
// baseline (speedup 1.0000x reference)
#include <cuda_runtime.h>
#include <cstdint>

#define BB   2
#define SS   2048
#define HIDD 1024
#define NHH  4
#define HDD  256

// Scratch (allocation-free rule -> __device__ globals)
__device__ float g_q[BB*NHH*SS*HDD];
__device__ float g_k[BB*NHH*SS*HDD];
__device__ float g_v[BB*NHH*SS*HDD];
__device__ float g_o[BB*SS*HIDD];
// pre-rounded (tf32-in-fp32) operand copies
__device__ float g_ha[BB*SS*HIDD];
__device__ float g_wq[3*HIDD*HIDD];
__device__ float g_wo[HIDD*HIDD];

// ---------------------------------------------------------------------------
// helpers (base PTX ISA, works on sm_103 target)
// ---------------------------------------------------------------------------
__device__ __forceinline__ void mma168(float* c, const uint32_t* a, const uint32_t* b) {
    asm volatile(
        "mma.sync.aligned.m16n8k8.row.col.f32.tf32.tf32.f32 "
        "{%0,%1,%2,%3}, {%4,%5,%6,%7}, {%8,%9}, {%0,%1,%2,%3};"
        : "+f"(c[0]), "+f"(c[1]), "+f"(c[2]), "+f"(c[3])
        : "r"(a[0]), "r"(a[1]), "r"(a[2]), "r"(a[3]), "r"(b[0]), "r"(b[1]));
}
__device__ __forceinline__ uint32_t f2tf32(float x) {
    uint32_t u;
    asm("cvt.rna.tf32.f32 %0, %1;" : "=r"(u) : "f"(x));
    return u;
}
__device__ __forceinline__ float roundtf(float x) {
    return __uint_as_float(f2tf32(x));
}
__device__ __forceinline__ uint32_t smem_u32(const void* p) {
    uint32_t a;
    asm("{ .reg .u64 t; cvta.to.shared.u64 t, %1; cvt.u32.u64 %0, t; }"
        : "=r"(a) : "l"(p));
    return a;
}
// L1-caching async copy (16B). .ca keeps the line in L1 (unlike .cg).
__device__ __forceinline__ void cp_async16_ca(uint32_t saddr, const void* gptr) {
    asm volatile("cp.async.ca.shared.global [%0], [%1], 16;"
                 :: "r"(saddr), "l"(gptr) : "memory");
}
#define CP_COMMIT() asm volatile("cp.async.commit_group;" ::: "memory")
#define CP_WAIT(n)  asm volatile("cp.async.wait_group %0;" :: "n"(n) : "memory")
#define PAIR_BAR(id) asm volatile("bar.sync %0, 64;" :: "r"(id) : "memory")

// ---------------------------------------------------------------------------
// Kernel 0: elementwise tf32 pre-round
// ---------------------------------------------------------------------------
__global__ __launch_bounds__(256) void round_kernel(
    const float* __restrict__ src, float* __restrict__ dst, int n4)
{
    int i = blockIdx.x * 256 + threadIdx.x;
    if (i < n4) {
        float4 v = *(const float4*)(src + 4 * (size_t)i);
        *(float4*)(dst + 4 * (size_t)i) =
            make_float4(roundtf(v.x), roundtf(v.y), roundtf(v.z), roundtf(v.w));
    }
}

// ===========================================================================
// GEMM kernels: tf32 mma.sync, cp.async.ca 2-stage pipelined mainloop.
// Inputs must be pre-rounded to tf32.
// ===========================================================================
#define TSTR 36
#define GEMM_SMEM (4 * 128 * TSTR * 4)   // 2 stages x (A,B) x 128x36 words

extern __shared__ uint32_t gsm[];

__device__ __forceinline__ void mma_mainloop_ca(
    const float* __restrict__ A, const float* __restrict__ Bmat,
    int m0, int n0, float c[4][4][4])
{
    const int tid  = threadIdx.x;
    const int wid  = tid >> 5, lane = tid & 31;
    const int g    = lane >> 2, tg = lane & 3;
    const int warpM = wid >> 2, warpN = wid & 3;

    uint32_t* stA[2] = { gsm,                gsm + 128 * TSTR };
    uint32_t* stB[2] = { gsm + 2*128*TSTR,   gsm + 3*128*TSTR };

#pragma unroll
    for (int mt = 0; mt < 4; mt++)
#pragma unroll
        for (int nt = 0; nt < 4; nt++)
#pragma unroll
            for (int r = 0; r < 4; r++) c[mt][nt][r] = 0.f;

    // load slice: row = tid>>1, 16 floats at (tid&1)*16 (4x cp.async16)
    const int lrow = tid >> 1;
    const int lcw  = (tid & 1) * 16;
    const float* Agr = A    + (size_t)(m0 + lrow) * 1024 + lcw;
    const float* Bgr = Bmat + (size_t)(n0 + lrow) * 1024 + lcw;
    const uint32_t sa0 = smem_u32(stA[0]) + (uint32_t)(lrow * TSTR + lcw) * 4u;
    const uint32_t sa1 = smem_u32(stA[1]) + (uint32_t)(lrow * TSTR + lcw) * 4u;
    const uint32_t sb0 = smem_u32(stB[0]) + (uint32_t)(lrow * TSTR + lcw) * 4u;
    const uint32_t sb1 = smem_u32(stB[1]) + (uint32_t)(lrow * TSTR + lcw) * 4u;

    // prologue: stage 0 <- kt 0
#pragma unroll
    for (int j = 0; j < 4; j++) {
        cp_async16_ca(sa0 + 16u * j, Agr + 4 * j);
        cp_async16_ca(sb0 + 16u * j, Bgr + 4 * j);
    }
    CP_COMMIT();

    for (int kt = 0; kt < 32; kt++) {
        const int st = kt & 1;
        if (kt < 31) {                          // stage st^1 <- kt+1
            const float* An = Agr + (kt + 1) * 32;
            const float* Bn = Bgr + (kt + 1) * 32;
            const uint32_t da = st ? sa0 : sa1;
            const uint32_t db = st ? sb0 : sb1;
#pragma unroll
            for (int j = 0; j < 4; j++) {
                cp_async16_ca(da + 16u * j, An + 4 * j);
                cp_async16_ca(db + 16u * j, Bn + 4 * j);
            }
            CP_COMMIT();
            CP_WAIT(1);                          // stage st ready
        } else {
            CP_WAIT(0);
        }
        __syncthreads();

        const uint32_t* As = stA[st];
        const uint32_t* Bs = stB[st];
#pragma unroll
        for (int ks = 0; ks < 4; ks++) {
            const int kk = ks * 8;
            uint32_t a[4][4], b[4][2];
#pragma unroll
            for (int mt = 0; mt < 4; mt++) {
                int r = warpM * 64 + mt * 16 + g;
                a[mt][0] = As[r * TSTR + kk + tg];
                a[mt][1] = As[(r + 8) * TSTR + kk + tg];
                a[mt][2] = As[r * TSTR + kk + tg + 4];
                a[mt][3] = As[(r + 8) * TSTR + kk + tg + 4];
            }
#pragma unroll
            for (int nt = 0; nt < 4; nt++) {
                int n = warpN * 32 + nt * 8 + g;
                b[nt][0] = Bs[n * TSTR + kk + tg];
                b[nt][1] = Bs[n * TSTR + kk + tg + 4];
            }
#pragma unroll
            for (int mt = 0; mt < 4; mt++)
#pragma unroll
                for (int nt = 0; nt < 4; nt++)
                    mma168(c[mt][nt], a[mt], b[nt]);
        }
        __syncthreads();   // stage st free for overwrite next iteration
    }
}

__global__ __launch_bounds__(256, 2) void qkv_mma_kernel(
    const float* __restrict__ A, const float* __restrict__ W,
    const float* __restrict__ fr, const float* __restrict__ fi)
{
    const int tid  = threadIdx.x;
    const int wid  = tid >> 5, lane = tid & 31;
    const int g    = lane >> 2, tg = lane & 3;
    const int warpM = wid >> 2, warpN = wid & 3;
    const int m0 = blockIdx.y * 128;
    const int n0 = blockIdx.x * 128;

    float c[4][4][4];
    mma_mainloop_ca(A, W, m0, n0, c);

    // Epilogue: RoPE + scatter, pre-rounded to tf32 for the attention kernel.
    const int which = n0 >> 10;
#pragma unroll
    for (int mt = 0; mt < 4; mt++) {
#pragma unroll
        for (int half = 0; half < 2; half++) {
            int m  = m0 + warpM * 64 + mt * 16 + g + half * 8;
            int bb = m >> 11;
            int ss = m & 2047;
#pragma unroll
            for (int nt = 0; nt < 4; nt++) {
                int n = n0 + warpN * 32 + nt * 8 + tg * 2;
                int h = (n >> 8) & 3;
                int d = n & 255;
                float x0 = c[mt][nt][half * 2];
                float x1 = c[mt][nt][half * 2 + 1];
                size_t oidx = (((size_t)(bb * NHH + h)) * SS + ss) * HDD + d;
                if (which == 2) {
                    *(float2*)&g_v[oidx] = make_float2(roundtf(x0), roundtf(x1));
                } else {
                    float fre = __ldg(&fr[(size_t)ss * 128 + (d >> 1)]);
                    float fim = __ldg(&fi[(size_t)ss * 128 + (d >> 1)]);
                    float o0 = x0 * fre - x1 * fim;
                    float o1 = x0 * fim + x1 * fre;
                    float* dst = (which == 0) ? g_q : g_k;
                    *(float2*)&dst[oidx] = make_float2(roundtf(o0), roundtf(o1));
                }
            }
        }
    }
}

__global__ __launch_bounds__(256, 2) void o_mma_kernel(
    const float* __restrict__ A, const float* __restrict__ W,
    float* __restrict__ C)
{
    const int tid  = threadIdx.x;
    const int wid  = tid >> 5, lane = tid & 31;
    const int g    = lane >> 2, tg = lane & 3;
    const int warpM = wid >> 2, warpN = wid & 3;
    const int m0 = blockIdx.y * 128;
    const int n0 = blockIdx.x * 128;

    float c[4][4][4];
    mma_mainloop_ca(A, W, m0, n0, c);

#pragma unroll
    for (int mt = 0; mt < 4; mt++) {
#pragma unroll
        for (int half = 0; half < 2; half++) {
            int m = m0 + warpM * 64 + mt * 16 + g + half * 8;
#pragma unroll
            for (int nt = 0; nt < 4; nt++) {
                int n = n0 + warpN * 32 + nt * 8 + tg * 2;
                *(float2*)&C[(size_t)m * 1024 + n] =
                    make_float2(c[mt][nt][half * 2], c[mt][nt][half * 2 + 1]);
            }
        }
    }
}

// ===========================================================================
// Kernel 2: tensor-core causal flash attention (R12: 64x64, single-exchange
// softmax + named pair barriers). Unchanged.
// ===========================================================================
#define QSTR 260
#define VSTR 264
#define PSTR 68

extern __shared__ uint32_t attn_sm[];

__global__ __launch_bounds__(256, 1) void attn_mma_kernel(
    const float* __restrict__ qg, const float* __restrict__ kg,
    const float* __restrict__ vg, float* __restrict__ og)
{
    uint32_t* Qs = attn_sm;                 // [64][QSTR]
    uint32_t* Ks = Qs + 64 * QSTR;          // [64][QSTR]
    uint32_t* Vs = Ks + 64 * QSTR;          // [64][VSTR]
    uint32_t* Ps = Vs + 64 * VSTR;          // [64][PSTR]
    float* mS   = (float*)(Ps + 64 * PSTR); // [64]
    float* lS   = mS + 64;                  // [64]
    float* pmax = lS + 64;                  // [2][64]
    float* psum = pmax + 128;               // [2][64]

    const int tid  = threadIdx.x;
    const int wid  = tid >> 5, lane = tid & 31;
    const int g    = lane >> 2, tg = lane & 3;
    const int warpRow = wid >> 1;           // 0..3
    const int warpCol = wid & 1;            // 0..1
    const int barid   = warpRow + 1;        // named barrier per pair

    const int qt  = gridDim.x - 1 - blockIdx.x;   // heavy CTAs first
    const int q0  = qt * 64;
    const int h   = blockIdx.y;
    const int b   = blockIdx.z;
    const size_t base = ((size_t)(b * NHH + h)) * SS * HDD;
    const float scale = 0.0625f;                  // exact power of 2

    // load Q tile (scale exact -> stays tf32)
#pragma unroll
    for (int it = 0; it < 16; it++) {
        int f   = tid + it * 256;
        int row = f >> 6;
        int c4  = (f & 63) * 4;
        float4 v = *(const float4*)&qg[base + (size_t)(q0 + row) * HDD + c4];
        float4 w = make_float4(v.x * scale, v.y * scale, v.z * scale, v.w * scale);
        *(float4*)((float*)Qs + row * QSTR + c4) = w;
    }
    if (tid < 64) { mS[tid] = -1e30f; lS[tid] = 0.f; }

    float o[16][4];
#pragma unroll
    for (int nt = 0; nt < 16; nt++)
#pragma unroll
        for (int r = 0; r < 4; r++) o[nt][r] = 0.f;

    const int rg = warpRow * 16 + g;

    const int nkb = qt + 1;
    for (int kbi = 0; kbi < nkb; kbi++) {
        const int k0 = kbi * 64;
        __syncthreads();                    // all warps done with prev Ks/Vs/Ps

        // K,V tile copy (pre-rounded -> raw float4)
#pragma unroll
        for (int it = 0; it < 16; it++) {
            int f   = tid + it * 256;
            int row = f >> 6;
            int c4  = (f & 63) * 4;
            size_t gi = base + (size_t)(k0 + row) * HDD + c4;
            *(uint4*)&Ks[row * QSTR + c4] = *(const uint4*)&kg[gi];
            *(uint4*)&Vs[row * VSTR + c4] = *(const uint4*)&vg[gi];
        }
        __syncthreads();

        // ---- S = Q K^T : warp tile 16 x 32 ----
        float s[4][4];
#pragma unroll
        for (int nt = 0; nt < 4; nt++)
#pragma unroll
            for (int r = 0; r < 4; r++) s[nt][r] = 0.f;

#pragma unroll 4
        for (int kk = 0; kk < 256; kk += 8) {
            uint32_t a[4];
            a[0] = Qs[rg * QSTR + kk + tg];
            a[1] = Qs[(rg + 8) * QSTR + kk + tg];
            a[2] = Qs[rg * QSTR + kk + tg + 4];
            a[3] = Qs[(rg + 8) * QSTR + kk + tg + 4];
#pragma unroll
            for (int nt = 0; nt < 4; nt++) {
                int n = warpCol * 32 + nt * 8 + g;
                uint32_t bb2[2];
                bb2[0] = Ks[n * QSTR + kk + tg];
                bb2[1] = Ks[n * QSTR + kk + tg + 4];
                mma168(s[nt], a, bb2);
            }
        }

        // causal mask on diagonal tile
        if (kbi == qt) {
#pragma unroll
            for (int nt = 0; nt < 4; nt++) {
#pragma unroll
                for (int r = 0; r < 4; r++) {
                    int row = q0 + rg + ((r & 2) ? 8 : 0);
                    int col = k0 + warpCol * 32 + nt * 8 + 2 * tg + (r & 1);
                    if (col > row) s[nt][r] = -1e30f;
                }
            }
        }

        // ---- single-exchange online softmax ----
        float mx0 = -1e30f, mx1 = -1e30f;
#pragma unroll
        for (int nt = 0; nt < 4; nt++) {
            mx0 = fmaxf(mx0, fmaxf(s[nt][0], s[nt][1]));
            mx1 = fmaxf(mx1, fmaxf(s[nt][2], s[nt][3]));
        }
        mx0 = fmaxf(mx0, __shfl_xor_sync(0xffffffffu, mx0, 1));
        mx0 = fmaxf(mx0, __shfl_xor_sync(0xffffffffu, mx0, 2));
        mx1 = fmaxf(mx1, __shfl_xor_sync(0xffffffffu, mx1, 1));
        mx1 = fmaxf(mx1, __shfl_xor_sync(0xffffffffu, mx1, 2));

        float p[4][4];
        float sum0 = 0.f, sum1 = 0.f;
#pragma unroll
        for (int nt = 0; nt < 4; nt++) {
            p[nt][0] = __expf(s[nt][0] - mx0);
            p[nt][1] = __expf(s[nt][1] - mx0);
            p[nt][2] = __expf(s[nt][2] - mx1);
            p[nt][3] = __expf(s[nt][3] - mx1);
            sum0 += p[nt][0] + p[nt][1];
            sum1 += p[nt][2] + p[nt][3];
        }
        sum0 += __shfl_xor_sync(0xffffffffu, sum0, 1);
        sum0 += __shfl_xor_sync(0xffffffffu, sum0, 2);
        sum1 += __shfl_xor_sync(0xffffffffu, sum1, 1);
        sum1 += __shfl_xor_sync(0xffffffffu, sum1, 2);
        if (tg == 0) {
            pmax[warpCol * 64 + rg]     = mx0;
            pmax[warpCol * 64 + rg + 8] = mx1;
            psum[warpCol * 64 + rg]     = sum0;
            psum[warpCol * 64 + rg + 8] = sum1;
        }
        PAIR_BAR(barid);                    // exchange (mx, sum) within pair

        const int oc = warpCol ^ 1;
        float mxo0 = pmax[oc * 64 + rg],     sumo0 = psum[oc * 64 + rg];
        float mxo1 = pmax[oc * 64 + rg + 8], sumo1 = psum[oc * 64 + rg + 8];

        float m0old = mS[rg], m1old = mS[rg + 8];
        float m0 = fmaxf(m0old, fmaxf(mx0, mxo0));
        float m1 = fmaxf(m1old, fmaxf(mx1, mxo1));
        float resc0 = __expf(m0old - m0);
        float resc1 = __expf(m1old - m1);
        float f0 = __expf(mx0 - m0);
        float f1 = __expf(mx1 - m1);

        const int cl = warpCol * 32 + 2 * tg;
#pragma unroll
        for (int nt = 0; nt < 4; nt++) {
            Ps[rg * PSTR + cl + nt * 8]           = f2tf32(p[nt][0] * f0);
            Ps[rg * PSTR + cl + nt * 8 + 1]       = f2tf32(p[nt][1] * f0);
            Ps[(rg + 8) * PSTR + cl + nt * 8]     = f2tf32(p[nt][2] * f1);
            Ps[(rg + 8) * PSTR + cl + nt * 8 + 1] = f2tf32(p[nt][3] * f1);
        }

        if (warpCol == 0 && tg == 0) {
            lS[rg]     = lS[rg]     * resc0 + sum0 * f0 + sumo0 * __expf(mxo0 - m0);
            lS[rg + 8] = lS[rg + 8] * resc1 + sum1 * f1 + sumo1 * __expf(mxo1 - m1);
            mS[rg]     = m0;
            mS[rg + 8] = m1;
        }
        PAIR_BAR(barid);                    // P (and stats) visible within pair

        // ---- O = O*resc + P V : warp tile 16 x 128 ----
#pragma unroll
        for (int nt = 0; nt < 16; nt++) {
            o[nt][0] *= resc0; o[nt][1] *= resc0;
            o[nt][2] *= resc1; o[nt][3] *= resc1;
        }
#pragma unroll
        for (int kk8 = 0; kk8 < 8; kk8++) {
            const int kk = kk8 * 8;
            uint32_t a[4];
            a[0] = Ps[rg * PSTR + kk + tg];
            a[1] = Ps[(rg + 8) * PSTR + kk + tg];
            a[2] = Ps[rg * PSTR + kk + tg + 4];
            a[3] = Ps[(rg + 8) * PSTR + kk + tg + 4];
#pragma unroll
            for (int nt = 0; nt < 16; nt++) {
                int n = warpCol * 128 + nt * 8 + g;
                uint32_t bb2[2];
                bb2[0] = Vs[(kk + tg) * VSTR + n];
                bb2[1] = Vs[(kk + tg + 4) * VSTR + n];
                mma168(o[nt], a, bb2);
            }
        }
    }
    __syncthreads();

    // epilogue: normalize + write, pre-rounded for the O-projection tf32 GEMM
    float linv0 = 1.f / lS[rg];
    float linv1 = 1.f / lS[rg + 8];
    size_t ob0 = ((size_t)b * SS + (q0 + rg))     * HIDD + h * HDD;
    size_t ob1 = ((size_t)b * SS + (q0 + rg + 8)) * HIDD + h * HDD;
#pragma unroll
    for (int nt = 0; nt < 16; nt++) {
        int col = warpCol * 128 + nt * 8 + 2 * tg;
        *(float2*)&og[ob0 + col] = make_float2(roundtf(o[nt][0] * linv0),
                                               roundtf(o[nt][1] * linv0));
        *(float2*)&og[ob1 + col] = make_float2(roundtf(o[nt][2] * linv1),
                                               roundtf(o[nt][3] * linv1));
    }
}

// ---------------------------------------------------------------------------
extern "C" void kernel_launch(void* const* d_in, const int* in_sizes, int n_in,
                              void* d_out, int out_size)
{
    const float* hidden = (const float*)d_in[0];
    const float* fr     = (const float*)d_in[1];
    const float* fi     = (const float*)d_in[2];
    // d_in[3] = mask (causal handled analytically)
    const float* Wqkv   = (const float*)d_in[4];
    const float* Wo     = (const float*)d_in[5];
    float* out = (float*)d_out;

    float *qb, *kb, *vb, *ob, *hab, *wqb, *wob;
    cudaGetSymbolAddress((void**)&qb,  g_q);
    cudaGetSymbolAddress((void**)&kb,  g_k);
    cudaGetSymbolAddress((void**)&vb,  g_v);
    cudaGetSymbolAddress((void**)&ob,  g_o);
    cudaGetSymbolAddress((void**)&hab, g_ha);
    cudaGetSymbolAddress((void**)&wqb, g_wq);
    cudaGetSymbolAddress((void**)&wob, g_wo);

    // 0) pre-round operands to tf32
    round_kernel<<<(BB*SS*HIDD/4 + 255)/256, 256>>>(hidden, hab, BB*SS*HIDD/4);
    round_kernel<<<(3*HIDD*HIDD/4 + 255)/256, 256>>>(Wqkv, wqb, 3*HIDD*HIDD/4);
    round_kernel<<<(HIDD*HIDD/4 + 255)/256, 256>>>(Wo, wob, HIDD*HIDD/4);

    // 1) QKV + RoPE (cp.async.ca pipelined, occ 2)
    cudaFuncSetAttribute(qkv_mma_kernel, cudaFuncAttributeMaxDynamicSharedMemorySize, GEMM_SMEM);
    dim3 g1(3072 / 128, 4096 / 128);
    qkv_mma_kernel<<<g1, 256, GEMM_SMEM>>>(hab, wqb, fr, fi);

    // 2) tensor-core flash attention (R12)
    const int asmB = (64 * QSTR + 64 * QSTR + 64 * VSTR + 64 * PSTR + 64 * 2 + 128 * 2) * 4;
    cudaFuncSetAttribute(attn_mma_kernel, cudaFuncAttributeMaxDynamicSharedMemorySize, asmB);
    dim3 g2(SS / 64, NHH, BB);
    attn_mma_kernel<<<g2, 256, asmB>>>(qb, kb, vb, ob);

    // 3) output projection (cp.async.ca pipelined, occ 2)
    cudaFuncSetAttribute(o_mma_kernel, cudaFuncAttributeMaxDynamicSharedMemorySize, GEMM_SMEM);
    dim3 g3(1024 / 128, 4096 / 128);
    o_mma_kernel<<<g3, 256, GEMM_SMEM>>>(ob, wob, out);
}

// round 14
// speedup vs baseline: 1.0968x; 1.0968x over previous
#include <cuda_runtime.h>
#include <cstdint>

#define BB   2
#define SS   2048
#define HIDD 1024
#define NHH  4
#define HDD  256

// Scratch (allocation-free rule -> __device__ globals)
__device__ float g_q[BB*NHH*SS*HDD];
__device__ float g_k[BB*NHH*SS*HDD];
__device__ float g_v[BB*NHH*SS*HDD];
__device__ float g_o[BB*SS*HIDD];

// ---------------------------------------------------------------------------
// helpers (base PTX ISA, works on sm_103 target)
// ---------------------------------------------------------------------------
__device__ __forceinline__ void mma168(float* c, const uint32_t* a, const uint32_t* b) {
    asm volatile(
        "mma.sync.aligned.m16n8k8.row.col.f32.tf32.tf32.f32 "
        "{%0,%1,%2,%3}, {%4,%5,%6,%7}, {%8,%9}, {%0,%1,%2,%3};"
        : "+f"(c[0]), "+f"(c[1]), "+f"(c[2]), "+f"(c[3])
        : "r"(a[0]), "r"(a[1]), "r"(a[2]), "r"(a[3]), "r"(b[0]), "r"(b[1]));
}
__device__ __forceinline__ uint32_t f2tf32(float x) {
    uint32_t u;
    asm("cvt.rna.tf32.f32 %0, %1;" : "=r"(u) : "f"(x));
    return u;
}
__device__ __forceinline__ float roundtf(float x) {
    return __uint_as_float(f2tf32(x));
}
#define PAIR_BAR(id) asm volatile("bar.sync %0, 64;" :: "r"(id) : "memory")

// ===========================================================================
// GEMM kernels: tf32 mma.sync. 64-k tile stored as TWO R9-style 32-k
// sub-tiles (identical per-sub-tile layout/bank behavior; half the barriers).
// Dynamic smem: 2 x 128 x 36 words for A, same for B = 72KB -> occ 2.
// ===========================================================================
#define TSTR 36
#define SUBT (128 * TSTR)                 // words per 32-k sub-tile
#define GEMM_SMEM (4 * SUBT * 4)          // (A0,A1,B0,B1) bytes = 73728

extern __shared__ uint32_t gsm[];

__device__ __forceinline__ void mma_mainloop(
    const float* __restrict__ A, const float* __restrict__ Bmat,
    int m0, int n0, float c[4][4][4])
{
    uint32_t* As = gsm;                   // [2][128][36]
    uint32_t* Bs = gsm + 2 * SUBT;        // [2][128][36]

    const int tid  = threadIdx.x;
    const int wid  = tid >> 5, lane = tid & 31;
    const int g    = lane >> 2, tg = lane & 3;
    const int warpM = wid >> 2, warpN = wid & 3;

#pragma unroll
    for (int mt = 0; mt < 4; mt++)
#pragma unroll
        for (int nt = 0; nt < 4; nt++)
#pragma unroll
            for (int r = 0; r < 4; r++) c[mt][nt][r] = 0.f;

    for (int kt = 0; kt < 16; kt++) {
        const int k0 = kt * 64;
        __syncthreads();
        // fill both 32-k sub-tiles (R9 mapping each)
#pragma unroll
        for (int half = 0; half < 2; half++) {
            const float* Ag = A    + (size_t)m0 * 1024 + k0 + half * 32;
            const float* Bg = Bmat + (size_t)n0 * 1024 + k0 + half * 32;
            uint32_t* Ad = As + half * SUBT;
            uint32_t* Bd = Bs + half * SUBT;
#pragma unroll
            for (int j = 0; j < 4; j++) {
                int f   = tid * 4 + j;
                int row = f >> 3;
                int cw  = (f & 7) * 4;
                float4 va = *(const float4*)(Ag + (size_t)row * 1024 + cw);
                float4 vb = *(const float4*)(Bg + (size_t)row * 1024 + cw);
                *(uint4*)&Ad[row * TSTR + cw] =
                    make_uint4(f2tf32(va.x), f2tf32(va.y), f2tf32(va.z), f2tf32(va.w));
                *(uint4*)&Bd[row * TSTR + cw] =
                    make_uint4(f2tf32(vb.x), f2tf32(vb.y), f2tf32(vb.z), f2tf32(vb.w));
            }
        }
        __syncthreads();

#pragma unroll
        for (int ks8 = 0; ks8 < 8; ks8++) {
            const uint32_t* Asub = As + (ks8 >> 2) * SUBT;
            const uint32_t* Bsub = Bs + (ks8 >> 2) * SUBT;
            const int kk = (ks8 & 3) * 8;
            uint32_t a[4][4], b[4][2];
#pragma unroll
            for (int mt = 0; mt < 4; mt++) {
                int r = warpM * 64 + mt * 16 + g;
                a[mt][0] = Asub[r * TSTR + kk + tg];
                a[mt][1] = Asub[(r + 8) * TSTR + kk + tg];
                a[mt][2] = Asub[r * TSTR + kk + tg + 4];
                a[mt][3] = Asub[(r + 8) * TSTR + kk + tg + 4];
            }
#pragma unroll
            for (int nt = 0; nt < 4; nt++) {
                int n = warpN * 32 + nt * 8 + g;
                b[nt][0] = Bsub[n * TSTR + kk + tg];
                b[nt][1] = Bsub[n * TSTR + kk + tg + 4];
            }
#pragma unroll
            for (int mt = 0; mt < 4; mt++)
#pragma unroll
                for (int nt = 0; nt < 4; nt++)
                    mma168(c[mt][nt], a[mt], b[nt]);
        }
    }
}

__global__ __launch_bounds__(256, 2) void qkv_mma_kernel(
    const float* __restrict__ A, const float* __restrict__ W,
    const float* __restrict__ fr, const float* __restrict__ fi)
{
    const int tid  = threadIdx.x;
    const int wid  = tid >> 5, lane = tid & 31;
    const int g    = lane >> 2, tg = lane & 3;
    const int warpM = wid >> 2, warpN = wid & 3;
    const int m0 = blockIdx.y * 128;
    const int n0 = blockIdx.x * 128;

    float c[4][4][4];
    mma_mainloop(A, W, m0, n0, c);

    // Epilogue: RoPE + scatter, PRE-ROUNDED to tf32 for the attention kernel.
    const int which = n0 >> 10;
#pragma unroll
    for (int mt = 0; mt < 4; mt++) {
#pragma unroll
        for (int half = 0; half < 2; half++) {
            int m  = m0 + warpM * 64 + mt * 16 + g + half * 8;
            int bb = m >> 11;
            int ss = m & 2047;
#pragma unroll
            for (int nt = 0; nt < 4; nt++) {
                int n = n0 + warpN * 32 + nt * 8 + tg * 2;
                int h = (n >> 8) & 3;
                int d = n & 255;
                float x0 = c[mt][nt][half * 2];
                float x1 = c[mt][nt][half * 2 + 1];
                size_t oidx = (((size_t)(bb * NHH + h)) * SS + ss) * HDD + d;
                if (which == 2) {
                    *(float2*)&g_v[oidx] = make_float2(roundtf(x0), roundtf(x1));
                } else {
                    float fre = __ldg(&fr[(size_t)ss * 128 + (d >> 1)]);
                    float fim = __ldg(&fi[(size_t)ss * 128 + (d >> 1)]);
                    float o0 = x0 * fre - x1 * fim;
                    float o1 = x0 * fim + x1 * fre;
                    float* dst = (which == 0) ? g_q : g_k;
                    *(float2*)&dst[oidx] = make_float2(roundtf(o0), roundtf(o1));
                }
            }
        }
    }
}

__global__ __launch_bounds__(256, 2) void o_mma_kernel(
    const float* __restrict__ A, const float* __restrict__ W,
    float* __restrict__ C)
{
    const int tid  = threadIdx.x;
    const int wid  = tid >> 5, lane = tid & 31;
    const int g    = lane >> 2, tg = lane & 3;
    const int warpM = wid >> 2, warpN = wid & 3;
    const int m0 = blockIdx.y * 128;
    const int n0 = blockIdx.x * 128;

    float c[4][4][4];
    mma_mainloop(A, W, m0, n0, c);

#pragma unroll
    for (int mt = 0; mt < 4; mt++) {
#pragma unroll
        for (int half = 0; half < 2; half++) {
            int m = m0 + warpM * 64 + mt * 16 + g + half * 8;
#pragma unroll
            for (int nt = 0; nt < 4; nt++) {
                int n = n0 + warpN * 32 + nt * 8 + tg * 2;
                *(float2*)&C[(size_t)m * 1024 + n] =
                    make_float2(c[mt][nt][half * 2], c[mt][nt][half * 2 + 1]);
            }
        }
    }
}

// ===========================================================================
// Kernel 2: tensor-core causal flash attention (R12: 64x64, single-exchange
// softmax + named pair barriers). Unchanged.
// ===========================================================================
#define QSTR 260
#define VSTR 264
#define PSTR 68

extern __shared__ uint32_t attn_sm[];

__global__ __launch_bounds__(256, 1) void attn_mma_kernel(
    const float* __restrict__ qg, const float* __restrict__ kg,
    const float* __restrict__ vg, float* __restrict__ og)
{
    uint32_t* Qs = attn_sm;                 // [64][QSTR]
    uint32_t* Ks = Qs + 64 * QSTR;          // [64][QSTR]
    uint32_t* Vs = Ks + 64 * QSTR;          // [64][VSTR]
    uint32_t* Ps = Vs + 64 * VSTR;          // [64][PSTR]
    float* mS   = (float*)(Ps + 64 * PSTR); // [64]
    float* lS   = mS + 64;                  // [64]
    float* pmax = lS + 64;                  // [2][64]
    float* psum = pmax + 128;               // [2][64]

    const int tid  = threadIdx.x;
    const int wid  = tid >> 5, lane = tid & 31;
    const int g    = lane >> 2, tg = lane & 3;
    const int warpRow = wid >> 1;           // 0..3
    const int warpCol = wid & 1;            // 0..1
    const int barid   = warpRow + 1;        // named barrier per pair

    const int qt  = gridDim.x - 1 - blockIdx.x;   // heavy CTAs first
    const int q0  = qt * 64;
    const int h   = blockIdx.y;
    const int b   = blockIdx.z;
    const size_t base = ((size_t)(b * NHH + h)) * SS * HDD;
    const float scale = 0.0625f;                  // exact power of 2

    // load Q tile (scale exact -> stays tf32)
#pragma unroll
    for (int it = 0; it < 16; it++) {
        int f   = tid + it * 256;
        int row = f >> 6;
        int c4  = (f & 63) * 4;
        float4 v = *(const float4*)&qg[base + (size_t)(q0 + row) * HDD + c4];
        float4 w = make_float4(v.x * scale, v.y * scale, v.z * scale, v.w * scale);
        *(float4*)((float*)Qs + row * QSTR + c4) = w;
    }
    if (tid < 64) { mS[tid] = -1e30f; lS[tid] = 0.f; }

    float o[16][4];
#pragma unroll
    for (int nt = 0; nt < 16; nt++)
#pragma unroll
        for (int r = 0; r < 4; r++) o[nt][r] = 0.f;

    const int rg = warpRow * 16 + g;

    const int nkb = qt + 1;
    for (int kbi = 0; kbi < nkb; kbi++) {
        const int k0 = kbi * 64;
        __syncthreads();                    // all warps done with prev Ks/Vs/Ps

        // K,V tile copy (pre-rounded -> raw float4)
#pragma unroll
        for (int it = 0; it < 16; it++) {
            int f   = tid + it * 256;
            int row = f >> 6;
            int c4  = (f & 63) * 4;
            size_t gi = base + (size_t)(k0 + row) * HDD + c4;
            *(uint4*)&Ks[row * QSTR + c4] = *(const uint4*)&kg[gi];
            *(uint4*)&Vs[row * VSTR + c4] = *(const uint4*)&vg[gi];
        }
        __syncthreads();

        // ---- S = Q K^T : warp tile 16 x 32 ----
        float s[4][4];
#pragma unroll
        for (int nt = 0; nt < 4; nt++)
#pragma unroll
            for (int r = 0; r < 4; r++) s[nt][r] = 0.f;

#pragma unroll 4
        for (int kk = 0; kk < 256; kk += 8) {
            uint32_t a[4];
            a[0] = Qs[rg * QSTR + kk + tg];
            a[1] = Qs[(rg + 8) * QSTR + kk + tg];
            a[2] = Qs[rg * QSTR + kk + tg + 4];
            a[3] = Qs[(rg + 8) * QSTR + kk + tg + 4];
#pragma unroll
            for (int nt = 0; nt < 4; nt++) {
                int n = warpCol * 32 + nt * 8 + g;
                uint32_t bb2[2];
                bb2[0] = Ks[n * QSTR + kk + tg];
                bb2[1] = Ks[n * QSTR + kk + tg + 4];
                mma168(s[nt], a, bb2);
            }
        }

        // causal mask on diagonal tile
        if (kbi == qt) {
#pragma unroll
            for (int nt = 0; nt < 4; nt++) {
#pragma unroll
                for (int r = 0; r < 4; r++) {
                    int row = q0 + rg + ((r & 2) ? 8 : 0);
                    int col = k0 + warpCol * 32 + nt * 8 + 2 * tg + (r & 1);
                    if (col > row) s[nt][r] = -1e30f;
                }
            }
        }

        // ---- single-exchange online softmax ----
        float mx0 = -1e30f, mx1 = -1e30f;
#pragma unroll
        for (int nt = 0; nt < 4; nt++) {
            mx0 = fmaxf(mx0, fmaxf(s[nt][0], s[nt][1]));
            mx1 = fmaxf(mx1, fmaxf(s[nt][2], s[nt][3]));
        }
        mx0 = fmaxf(mx0, __shfl_xor_sync(0xffffffffu, mx0, 1));
        mx0 = fmaxf(mx0, __shfl_xor_sync(0xffffffffu, mx0, 2));
        mx1 = fmaxf(mx1, __shfl_xor_sync(0xffffffffu, mx1, 1));
        mx1 = fmaxf(mx1, __shfl_xor_sync(0xffffffffu, mx1, 2));

        float p[4][4];
        float sum0 = 0.f, sum1 = 0.f;
#pragma unroll
        for (int nt = 0; nt < 4; nt++) {
            p[nt][0] = __expf(s[nt][0] - mx0);
            p[nt][1] = __expf(s[nt][1] - mx0);
            p[nt][2] = __expf(s[nt][2] - mx1);
            p[nt][3] = __expf(s[nt][3] - mx1);
            sum0 += p[nt][0] + p[nt][1];
            sum1 += p[nt][2] + p[nt][3];
        }
        sum0 += __shfl_xor_sync(0xffffffffu, sum0, 1);
        sum0 += __shfl_xor_sync(0xffffffffu, sum0, 2);
        sum1 += __shfl_xor_sync(0xffffffffu, sum1, 1);
        sum1 += __shfl_xor_sync(0xffffffffu, sum1, 2);
        if (tg == 0) {
            pmax[warpCol * 64 + rg]     = mx0;
            pmax[warpCol * 64 + rg + 8] = mx1;
            psum[warpCol * 64 + rg]     = sum0;
            psum[warpCol * 64 + rg + 8] = sum1;
        }
        PAIR_BAR(barid);                    // exchange (mx, sum) within pair

        const int oc = warpCol ^ 1;
        float mxo0 = pmax[oc * 64 + rg],     sumo0 = psum[oc * 64 + rg];
        float mxo1 = pmax[oc * 64 + rg + 8], sumo1 = psum[oc * 64 + rg + 8];

        float m0old = mS[rg], m1old = mS[rg + 8];
        float m0 = fmaxf(m0old, fmaxf(mx0, mxo0));
        float m1 = fmaxf(m1old, fmaxf(mx1, mxo1));
        float resc0 = __expf(m0old - m0);
        float resc1 = __expf(m1old - m1);
        float f0 = __expf(mx0 - m0);
        float f1 = __expf(mx1 - m1);

        const int cl = warpCol * 32 + 2 * tg;
#pragma unroll
        for (int nt = 0; nt < 4; nt++) {
            Ps[rg * PSTR + cl + nt * 8]           = f2tf32(p[nt][0] * f0);
            Ps[rg * PSTR + cl + nt * 8 + 1]       = f2tf32(p[nt][1] * f0);
            Ps[(rg + 8) * PSTR + cl + nt * 8]     = f2tf32(p[nt][2] * f1);
            Ps[(rg + 8) * PSTR + cl + nt * 8 + 1] = f2tf32(p[nt][3] * f1);
        }

        if (warpCol == 0 && tg == 0) {
            lS[rg]     = lS[rg]     * resc0 + sum0 * f0 + sumo0 * __expf(mxo0 - m0);
            lS[rg + 8] = lS[rg + 8] * resc1 + sum1 * f1 + sumo1 * __expf(mxo1 - m1);
            mS[rg]     = m0;
            mS[rg + 8] = m1;
        }
        PAIR_BAR(barid);                    // P (and stats) visible within pair

        // ---- O = O*resc + P V : warp tile 16 x 128 ----
#pragma unroll
        for (int nt = 0; nt < 16; nt++) {
            o[nt][0] *= resc0; o[nt][1] *= resc0;
            o[nt][2] *= resc1; o[nt][3] *= resc1;
        }
#pragma unroll
        for (int kk8 = 0; kk8 < 8; kk8++) {
            const int kk = kk8 * 8;
            uint32_t a[4];
            a[0] = Ps[rg * PSTR + kk + tg];
            a[1] = Ps[(rg + 8) * PSTR + kk + tg];
            a[2] = Ps[rg * PSTR + kk + tg + 4];
            a[3] = Ps[(rg + 8) * PSTR + kk + tg + 4];
#pragma unroll
            for (int nt = 0; nt < 16; nt++) {
                int n = warpCol * 128 + nt * 8 + g;
                uint32_t bb2[2];
                bb2[0] = Vs[(kk + tg) * VSTR + n];
                bb2[1] = Vs[(kk + tg + 4) * VSTR + n];
                mma168(o[nt], a, bb2);
            }
        }
    }
    __syncthreads();

    // epilogue: normalize + write
    float linv0 = 1.f / lS[rg];
    float linv1 = 1.f / lS[rg + 8];
    size_t ob0 = ((size_t)b * SS + (q0 + rg))     * HIDD + h * HDD;
    size_t ob1 = ((size_t)b * SS + (q0 + rg + 8)) * HIDD + h * HDD;
#pragma unroll
    for (int nt = 0; nt < 16; nt++) {
        int col = warpCol * 128 + nt * 8 + 2 * tg;
        *(float2*)&og[ob0 + col] = make_float2(o[nt][0] * linv0, o[nt][1] * linv0);
        *(float2*)&og[ob1 + col] = make_float2(o[nt][2] * linv1, o[nt][3] * linv1);
    }
}

// ---------------------------------------------------------------------------
extern "C" void kernel_launch(void* const* d_in, const int* in_sizes, int n_in,
                              void* d_out, int out_size)
{
    const float* hidden = (const float*)d_in[0];
    const float* fr     = (const float*)d_in[1];
    const float* fi     = (const float*)d_in[2];
    // d_in[3] = mask (causal handled analytically)
    const float* Wqkv   = (const float*)d_in[4];
    const float* Wo     = (const float*)d_in[5];
    float* out = (float*)d_out;

    float *qb, *kb, *vb, *ob;
    cudaGetSymbolAddress((void**)&qb, g_q);
    cudaGetSymbolAddress((void**)&kb, g_k);
    cudaGetSymbolAddress((void**)&vb, g_v);
    cudaGetSymbolAddress((void**)&ob, g_o);

    // 1) QKV + RoPE on tf32 mma.sync (64-k tiles, occ 2)
    cudaFuncSetAttribute(qkv_mma_kernel, cudaFuncAttributeMaxDynamicSharedMemorySize, GEMM_SMEM);
    dim3 g1(3072 / 128, 4096 / 128);
    qkv_mma_kernel<<<g1, 256, GEMM_SMEM>>>(hidden, Wqkv, fr, fi);

    // 2) tensor-core flash attention (R12, unchanged)
    const int asmB = (64 * QSTR + 64 * QSTR + 64 * VSTR + 64 * PSTR + 64 * 2 + 128 * 2) * 4;
    cudaFuncSetAttribute(attn_mma_kernel, cudaFuncAttributeMaxDynamicSharedMemorySize, asmB);
    dim3 g2(SS / 64, NHH, BB);
    attn_mma_kernel<<<g2, 256, asmB>>>(qb, kb, vb, ob);

    // 3) output projection on tf32 mma.sync (64-k tiles, occ 2)
    cudaFuncSetAttribute(o_mma_kernel, cudaFuncAttributeMaxDynamicSharedMemorySize, GEMM_SMEM);
    dim3 g3(1024 / 128, 4096 / 128);
    o_mma_kernel<<<g3, 256, GEMM_SMEM>>>(ob, Wo, out);
}

// round 15
// speedup vs baseline: 1.1824x; 1.0780x over previous
#include <cuda_runtime.h>
#include <cstdint>

#define BB   2
#define SS   2048
#define HIDD 1024
#define NHH  4
#define HDD  256

// Scratch (allocation-free rule -> __device__ globals)
__device__ float g_q[BB*NHH*SS*HDD];
__device__ float g_k[BB*NHH*SS*HDD];
__device__ float g_v[BB*NHH*SS*HDD];
__device__ float g_o[BB*SS*HIDD];

// ---------------------------------------------------------------------------
// helpers (base PTX ISA, works on sm_103 target)
// ---------------------------------------------------------------------------
__device__ __forceinline__ void mma168(float* c, const uint32_t* a, const uint32_t* b) {
    asm volatile(
        "mma.sync.aligned.m16n8k8.row.col.f32.tf32.tf32.f32 "
        "{%0,%1,%2,%3}, {%4,%5,%6,%7}, {%8,%9}, {%0,%1,%2,%3};"
        : "+f"(c[0]), "+f"(c[1]), "+f"(c[2]), "+f"(c[3])
        : "r"(a[0]), "r"(a[1]), "r"(a[2]), "r"(a[3]), "r"(b[0]), "r"(b[1]));
}
__device__ __forceinline__ void ldsm_x4(uint32_t* r, uint32_t saddr) {
    asm volatile(
        "ldmatrix.sync.aligned.m8n8.x4.shared.b16 {%0,%1,%2,%3}, [%4];"
        : "=r"(r[0]), "=r"(r[1]), "=r"(r[2]), "=r"(r[3]) : "r"(saddr));
}
__device__ __forceinline__ uint32_t f2tf32(float x) {
    uint32_t u;
    asm("cvt.rna.tf32.f32 %0, %1;" : "=r"(u) : "f"(x));
    return u;
}
__device__ __forceinline__ float roundtf(float x) {
    return __uint_as_float(f2tf32(x));
}
__device__ __forceinline__ uint32_t smem_u32(const void* p) {
    uint32_t a;
    asm("{ .reg .u64 t; cvta.to.shared.u64 t, %1; cvt.u32.u64 %0, t; }"
        : "=r"(a) : "l"(p));
    return a;
}
#define PAIR_BAR(id) asm volatile("bar.sync %0, 64;" :: "r"(id) : "memory")

// ===========================================================================
// GEMM kernels: tf32 mma.sync, 64-k tile as two 32-k sub-tiles (R14),
// fragment loads via ldmatrix.x4.
// ===========================================================================
#define TSTR 36
#define SUBT (128 * TSTR)                 // words per 32-k sub-tile
#define GEMM_SMEM (4 * SUBT * 4)          // (A0,A1,B0,B1) bytes = 73728

extern __shared__ uint32_t gsm[];

__device__ __forceinline__ void mma_mainloop(
    const float* __restrict__ A, const float* __restrict__ Bmat,
    int m0, int n0, float c[4][4][4])
{
    uint32_t* As = gsm;                   // [2][128][36]
    uint32_t* Bs = gsm + 2 * SUBT;        // [2][128][36]

    const int tid  = threadIdx.x;
    const int wid  = tid >> 5, lane = tid & 31;
    const int warpM = wid >> 2, warpN = wid & 3;

    // ldmatrix per-thread base addresses (bytes)
    const uint32_t smA = smem_u32(As);
    const uint32_t smB = smem_u32(Bs);
    uint32_t aAd[4], aBd[2];
#pragma unroll
    for (int mt = 0; mt < 4; mt++) {
        int row = warpM * 64 + mt * 16 + (lane & 7) + ((lane & 8) ? 8 : 0);
        int co  = (lane & 16) ? 4 : 0;
        aAd[mt] = smA + (uint32_t)(row * TSTR + co) * 4u;
    }
#pragma unroll
    for (int p = 0; p < 2; p++) {
        int row = warpN * 32 + p * 16 + (lane & 7) + ((lane & 16) ? 8 : 0);
        int co  = (lane & 8) ? 4 : 0;
        aBd[p] = smB + (uint32_t)(row * TSTR + co) * 4u;
    }

#pragma unroll
    for (int mt = 0; mt < 4; mt++)
#pragma unroll
        for (int nt = 0; nt < 4; nt++)
#pragma unroll
            for (int r = 0; r < 4; r++) c[mt][nt][r] = 0.f;

    for (int kt = 0; kt < 16; kt++) {
        const int k0 = kt * 64;
        __syncthreads();
        // fill both 32-k sub-tiles (R9 mapping each)
#pragma unroll
        for (int half = 0; half < 2; half++) {
            const float* Ag = A    + (size_t)m0 * 1024 + k0 + half * 32;
            const float* Bg = Bmat + (size_t)n0 * 1024 + k0 + half * 32;
            uint32_t* Ad = As + half * SUBT;
            uint32_t* Bd = Bs + half * SUBT;
#pragma unroll
            for (int j = 0; j < 4; j++) {
                int f   = tid * 4 + j;
                int row = f >> 3;
                int cw  = (f & 7) * 4;
                float4 va = *(const float4*)(Ag + (size_t)row * 1024 + cw);
                float4 vb = *(const float4*)(Bg + (size_t)row * 1024 + cw);
                *(uint4*)&Ad[row * TSTR + cw] =
                    make_uint4(f2tf32(va.x), f2tf32(va.y), f2tf32(va.z), f2tf32(va.w));
                *(uint4*)&Bd[row * TSTR + cw] =
                    make_uint4(f2tf32(vb.x), f2tf32(vb.y), f2tf32(vb.z), f2tf32(vb.w));
            }
        }
        __syncthreads();

#pragma unroll
        for (int ks8 = 0; ks8 < 8; ks8++) {
            const uint32_t off = (uint32_t)((ks8 >> 2) * SUBT * 4 + (ks8 & 3) * 32);
            uint32_t a[4][4], b[2][4];
#pragma unroll
            for (int mt = 0; mt < 4; mt++) ldsm_x4(a[mt], aAd[mt] + off);
#pragma unroll
            for (int p = 0; p < 2; p++)    ldsm_x4(b[p],  aBd[p]  + off);
#pragma unroll
            for (int mt = 0; mt < 4; mt++) {
                mma168(c[mt][0], a[mt], &b[0][0]);
                mma168(c[mt][1], a[mt], &b[0][2]);
                mma168(c[mt][2], a[mt], &b[1][0]);
                mma168(c[mt][3], a[mt], &b[1][2]);
            }
        }
    }
}

__global__ __launch_bounds__(256, 2) void qkv_mma_kernel(
    const float* __restrict__ A, const float* __restrict__ W,
    const float* __restrict__ fr, const float* __restrict__ fi)
{
    const int tid  = threadIdx.x;
    const int wid  = tid >> 5, lane = tid & 31;
    const int g    = lane >> 2, tg = lane & 3;
    const int warpM = wid >> 2, warpN = wid & 3;
    const int m0 = blockIdx.y * 128;
    const int n0 = blockIdx.x * 128;

    float c[4][4][4];
    mma_mainloop(A, W, m0, n0, c);

    // Epilogue: RoPE + scatter, PRE-ROUNDED to tf32 for the attention kernel.
    const int which = n0 >> 10;
#pragma unroll
    for (int mt = 0; mt < 4; mt++) {
#pragma unroll
        for (int half = 0; half < 2; half++) {
            int m  = m0 + warpM * 64 + mt * 16 + g + half * 8;
            int bb = m >> 11;
            int ss = m & 2047;
#pragma unroll
            for (int nt = 0; nt < 4; nt++) {
                int n = n0 + warpN * 32 + nt * 8 + tg * 2;
                int h = (n >> 8) & 3;
                int d = n & 255;
                float x0 = c[mt][nt][half * 2];
                float x1 = c[mt][nt][half * 2 + 1];
                size_t oidx = (((size_t)(bb * NHH + h)) * SS + ss) * HDD + d;
                if (which == 2) {
                    *(float2*)&g_v[oidx] = make_float2(roundtf(x0), roundtf(x1));
                } else {
                    float fre = __ldg(&fr[(size_t)ss * 128 + (d >> 1)]);
                    float fim = __ldg(&fi[(size_t)ss * 128 + (d >> 1)]);
                    float o0 = x0 * fre - x1 * fim;
                    float o1 = x0 * fim + x1 * fre;
                    float* dst = (which == 0) ? g_q : g_k;
                    *(float2*)&dst[oidx] = make_float2(roundtf(o0), roundtf(o1));
                }
            }
        }
    }
}

__global__ __launch_bounds__(256, 2) void o_mma_kernel(
    const float* __restrict__ A, const float* __restrict__ W,
    float* __restrict__ C)
{
    const int tid  = threadIdx.x;
    const int wid  = tid >> 5, lane = tid & 31;
    const int g    = lane >> 2, tg = lane & 3;
    const int warpM = wid >> 2, warpN = wid & 3;
    const int m0 = blockIdx.y * 128;
    const int n0 = blockIdx.x * 128;

    float c[4][4][4];
    mma_mainloop(A, W, m0, n0, c);

#pragma unroll
    for (int mt = 0; mt < 4; mt++) {
#pragma unroll
        for (int half = 0; half < 2; half++) {
            int m = m0 + warpM * 64 + mt * 16 + g + half * 8;
#pragma unroll
            for (int nt = 0; nt < 4; nt++) {
                int n = n0 + warpN * 32 + nt * 8 + tg * 2;
                *(float2*)&C[(size_t)m * 1024 + n] =
                    make_float2(c[mt][nt][half * 2], c[mt][nt][half * 2 + 1]);
            }
        }
    }
}

// ===========================================================================
// Kernel 2: tensor-core causal flash attention (R12 structure) with
// ldmatrix fragment loads for S (a+b) and PV (a). PV b stays scalar LDS.
// ===========================================================================
#define QSTR 260
#define VSTR 264
#define PSTR 68

extern __shared__ uint32_t attn_sm[];

__global__ __launch_bounds__(256, 1) void attn_mma_kernel(
    const float* __restrict__ qg, const float* __restrict__ kg,
    const float* __restrict__ vg, float* __restrict__ og)
{
    uint32_t* Qs = attn_sm;                 // [64][QSTR]
    uint32_t* Ks = Qs + 64 * QSTR;          // [64][QSTR]
    uint32_t* Vs = Ks + 64 * QSTR;          // [64][VSTR]
    uint32_t* Ps = Vs + 64 * VSTR;          // [64][PSTR]
    float* mS   = (float*)(Ps + 64 * PSTR); // [64]
    float* lS   = mS + 64;                  // [64]
    float* pmax = lS + 64;                  // [2][64]
    float* psum = pmax + 128;               // [2][64]

    const int tid  = threadIdx.x;
    const int wid  = tid >> 5, lane = tid & 31;
    const int g    = lane >> 2, tg = lane & 3;
    const int warpRow = wid >> 1;           // 0..3
    const int warpCol = wid & 1;            // 0..1
    const int barid   = warpRow + 1;        // named barrier per pair

    const int qt  = gridDim.x - 1 - blockIdx.x;   // heavy CTAs first
    const int q0  = qt * 64;
    const int h   = blockIdx.y;
    const int b   = blockIdx.z;
    const size_t base = ((size_t)(b * NHH + h)) * SS * HDD;
    const float scale = 0.0625f;                  // exact power of 2

    // ldmatrix per-thread base addresses (bytes)
    const uint32_t qAd = smem_u32(Qs) +
        (uint32_t)((warpRow * 16 + (lane & 7) + ((lane & 8) ? 8 : 0)) * QSTR +
                   ((lane & 16) ? 4 : 0)) * 4u;
    const uint32_t kB0 = smem_u32(Ks) +
        (uint32_t)((warpCol * 32 + (lane & 7) + ((lane & 16) ? 8 : 0)) * QSTR +
                   ((lane & 8) ? 4 : 0)) * 4u;
    const uint32_t kB1 = kB0 + (uint32_t)(16 * QSTR) * 4u;
    const uint32_t pAd = smem_u32(Ps) +
        (uint32_t)((warpRow * 16 + (lane & 7) + ((lane & 8) ? 8 : 0)) * PSTR +
                   ((lane & 16) ? 4 : 0)) * 4u;

    // load Q tile (scale exact -> stays tf32)
#pragma unroll
    for (int it = 0; it < 16; it++) {
        int f   = tid + it * 256;
        int row = f >> 6;
        int c4  = (f & 63) * 4;
        float4 v = *(const float4*)&qg[base + (size_t)(q0 + row) * HDD + c4];
        float4 w = make_float4(v.x * scale, v.y * scale, v.z * scale, v.w * scale);
        *(float4*)((float*)Qs + row * QSTR + c4) = w;
    }
    if (tid < 64) { mS[tid] = -1e30f; lS[tid] = 0.f; }

    float o[16][4];
#pragma unroll
    for (int nt = 0; nt < 16; nt++)
#pragma unroll
        for (int r = 0; r < 4; r++) o[nt][r] = 0.f;

    const int rg = warpRow * 16 + g;

    const int nkb = qt + 1;
    for (int kbi = 0; kbi < nkb; kbi++) {
        const int k0 = kbi * 64;
        __syncthreads();                    // all warps done with prev Ks/Vs/Ps

        // K,V tile copy (pre-rounded -> raw float4)
#pragma unroll
        for (int it = 0; it < 16; it++) {
            int f   = tid + it * 256;
            int row = f >> 6;
            int c4  = (f & 63) * 4;
            size_t gi = base + (size_t)(k0 + row) * HDD + c4;
            *(uint4*)&Ks[row * QSTR + c4] = *(const uint4*)&kg[gi];
            *(uint4*)&Vs[row * VSTR + c4] = *(const uint4*)&vg[gi];
        }
        __syncthreads();

        // ---- S = Q K^T : warp tile 16 x 32, ldmatrix frags ----
        float s[4][4];
#pragma unroll
        for (int nt = 0; nt < 4; nt++)
#pragma unroll
            for (int r = 0; r < 4; r++) s[nt][r] = 0.f;

#pragma unroll 4
        for (int kk = 0; kk < 256; kk += 8) {
            uint32_t a[4], bk0[4], bk1[4];
            ldsm_x4(a,   qAd + kk * 4);
            ldsm_x4(bk0, kB0 + kk * 4);
            ldsm_x4(bk1, kB1 + kk * 4);
            mma168(s[0], a, &bk0[0]);
            mma168(s[1], a, &bk0[2]);
            mma168(s[2], a, &bk1[0]);
            mma168(s[3], a, &bk1[2]);
        }

        // causal mask on diagonal tile
        if (kbi == qt) {
#pragma unroll
            for (int nt = 0; nt < 4; nt++) {
#pragma unroll
                for (int r = 0; r < 4; r++) {
                    int row = q0 + rg + ((r & 2) ? 8 : 0);
                    int col = k0 + warpCol * 32 + nt * 8 + 2 * tg + (r & 1);
                    if (col > row) s[nt][r] = -1e30f;
                }
            }
        }

        // ---- single-exchange online softmax ----
        float mx0 = -1e30f, mx1 = -1e30f;
#pragma unroll
        for (int nt = 0; nt < 4; nt++) {
            mx0 = fmaxf(mx0, fmaxf(s[nt][0], s[nt][1]));
            mx1 = fmaxf(mx1, fmaxf(s[nt][2], s[nt][3]));
        }
        mx0 = fmaxf(mx0, __shfl_xor_sync(0xffffffffu, mx0, 1));
        mx0 = fmaxf(mx0, __shfl_xor_sync(0xffffffffu, mx0, 2));
        mx1 = fmaxf(mx1, __shfl_xor_sync(0xffffffffu, mx1, 1));
        mx1 = fmaxf(mx1, __shfl_xor_sync(0xffffffffu, mx1, 2));

        float p[4][4];
        float sum0 = 0.f, sum1 = 0.f;
#pragma unroll
        for (int nt = 0; nt < 4; nt++) {
            p[nt][0] = __expf(s[nt][0] - mx0);
            p[nt][1] = __expf(s[nt][1] - mx0);
            p[nt][2] = __expf(s[nt][2] - mx1);
            p[nt][3] = __expf(s[nt][3] - mx1);
            sum0 += p[nt][0] + p[nt][1];
            sum1 += p[nt][2] + p[nt][3];
        }
        sum0 += __shfl_xor_sync(0xffffffffu, sum0, 1);
        sum0 += __shfl_xor_sync(0xffffffffu, sum0, 2);
        sum1 += __shfl_xor_sync(0xffffffffu, sum1, 1);
        sum1 += __shfl_xor_sync(0xffffffffu, sum1, 2);
        if (tg == 0) {
            pmax[warpCol * 64 + rg]     = mx0;
            pmax[warpCol * 64 + rg + 8] = mx1;
            psum[warpCol * 64 + rg]     = sum0;
            psum[warpCol * 64 + rg + 8] = sum1;
        }
        PAIR_BAR(barid);                    // exchange (mx, sum) within pair

        const int oc = warpCol ^ 1;
        float mxo0 = pmax[oc * 64 + rg],     sumo0 = psum[oc * 64 + rg];
        float mxo1 = pmax[oc * 64 + rg + 8], sumo1 = psum[oc * 64 + rg + 8];

        float m0old = mS[rg], m1old = mS[rg + 8];
        float m0 = fmaxf(m0old, fmaxf(mx0, mxo0));
        float m1 = fmaxf(m1old, fmaxf(mx1, mxo1));
        float resc0 = __expf(m0old - m0);
        float resc1 = __expf(m1old - m1);
        float f0 = __expf(mx0 - m0);
        float f1 = __expf(mx1 - m1);

        const int cl = warpCol * 32 + 2 * tg;
#pragma unroll
        for (int nt = 0; nt < 4; nt++) {
            Ps[rg * PSTR + cl + nt * 8]           = f2tf32(p[nt][0] * f0);
            Ps[rg * PSTR + cl + nt * 8 + 1]       = f2tf32(p[nt][1] * f0);
            Ps[(rg + 8) * PSTR + cl + nt * 8]     = f2tf32(p[nt][2] * f1);
            Ps[(rg + 8) * PSTR + cl + nt * 8 + 1] = f2tf32(p[nt][3] * f1);
        }

        if (warpCol == 0 && tg == 0) {
            lS[rg]     = lS[rg]     * resc0 + sum0 * f0 + sumo0 * __expf(mxo0 - m0);
            lS[rg + 8] = lS[rg + 8] * resc1 + sum1 * f1 + sumo1 * __expf(mxo1 - m1);
            mS[rg]     = m0;
            mS[rg + 8] = m1;
        }
        PAIR_BAR(barid);                    // P (and stats) visible within pair

        // ---- O = O*resc + P V : warp tile 16 x 128 (ldmatrix a-frags) ----
#pragma unroll
        for (int nt = 0; nt < 16; nt++) {
            o[nt][0] *= resc0; o[nt][1] *= resc0;
            o[nt][2] *= resc1; o[nt][3] *= resc1;
        }
#pragma unroll
        for (int kk8 = 0; kk8 < 8; kk8++) {
            const int kk = kk8 * 8;
            uint32_t a[4];
            ldsm_x4(a, pAd + kk * 4);
#pragma unroll
            for (int nt = 0; nt < 16; nt++) {
                int n = warpCol * 128 + nt * 8 + g;
                uint32_t bb2[2];
                bb2[0] = Vs[(kk + tg) * VSTR + n];
                bb2[1] = Vs[(kk + tg + 4) * VSTR + n];
                mma168(o[nt], a, bb2);
            }
        }
    }
    __syncthreads();

    // epilogue: normalize + write
    float linv0 = 1.f / lS[rg];
    float linv1 = 1.f / lS[rg + 8];
    size_t ob0 = ((size_t)b * SS + (q0 + rg))     * HIDD + h * HDD;
    size_t ob1 = ((size_t)b * SS + (q0 + rg + 8)) * HIDD + h * HDD;
#pragma unroll
    for (int nt = 0; nt < 16; nt++) {
        int col = warpCol * 128 + nt * 8 + 2 * tg;
        *(float2*)&og[ob0 + col] = make_float2(o[nt][0] * linv0, o[nt][1] * linv0);
        *(float2*)&og[ob1 + col] = make_float2(o[nt][2] * linv1, o[nt][3] * linv1);
    }
}

// ---------------------------------------------------------------------------
extern "C" void kernel_launch(void* const* d_in, const int* in_sizes, int n_in,
                              void* d_out, int out_size)
{
    const float* hidden = (const float*)d_in[0];
    const float* fr     = (const float*)d_in[1];
    const float* fi     = (const float*)d_in[2];
    // d_in[3] = mask (causal handled analytically)
    const float* Wqkv   = (const float*)d_in[4];
    const float* Wo     = (const float*)d_in[5];
    float* out = (float*)d_out;

    float *qb, *kb, *vb, *ob;
    cudaGetSymbolAddress((void**)&qb, g_q);
    cudaGetSymbolAddress((void**)&kb, g_k);
    cudaGetSymbolAddress((void**)&vb, g_v);
    cudaGetSymbolAddress((void**)&ob, g_o);

    // 1) QKV + RoPE on tf32 mma.sync (64-k tiles, ldmatrix, occ 2)
    cudaFuncSetAttribute(qkv_mma_kernel, cudaFuncAttributeMaxDynamicSharedMemorySize, GEMM_SMEM);
    dim3 g1(3072 / 128, 4096 / 128);
    qkv_mma_kernel<<<g1, 256, GEMM_SMEM>>>(hidden, Wqkv, fr, fi);

    // 2) tensor-core flash attention (ldmatrix frags)
    const int asmB = (64 * QSTR + 64 * QSTR + 64 * VSTR + 64 * PSTR + 64 * 2 + 128 * 2) * 4;
    cudaFuncSetAttribute(attn_mma_kernel, cudaFuncAttributeMaxDynamicSharedMemorySize, asmB);
    dim3 g2(SS / 64, NHH, BB);
    attn_mma_kernel<<<g2, 256, asmB>>>(qb, kb, vb, ob);

    // 3) output projection on tf32 mma.sync (64-k tiles, ldmatrix, occ 2)
    cudaFuncSetAttribute(o_mma_kernel, cudaFuncAttributeMaxDynamicSharedMemorySize, GEMM_SMEM);
    dim3 g3(1024 / 128, 4096 / 128);
    o_mma_kernel<<<g3, 256, GEMM_SMEM>>>(ob, Wo, out);
}